// round 15
// baseline (speedup 1.0000x reference)
#include <cuda_runtime.h>
#include <cuda_fp16.h>
#include <cstdint>

#define BB 8
#define NN 2048
#define FIN 256
#define FOUT 64
#define LALPHA 0.2f
#define SPLIT 128
#define SPLITK 2
#define KSL (NN / SPLITK)
#define NCHUNK (KSL / 64)
#define CS_BLOCKS (BB * SPLIT)          // 1024 colsum blocks
#define PROJ_BLOCKS ((BB * NN) / 32)    // 512 projection blocks

// ---- scratch (device globals; no allocation) ----
__device__ float  g_WhL[BB * NN * FOUT];           // Wh*level fp32 (4 MB)
__device__ __half g_WhLh[BB * NN * FOUT];          // scaled fp16 (2 MB)
__device__ float  g_f1[BB * NN];
__device__ float  g_f2[BB * NN];
__device__ float  g_part[SPLIT * BB * NN];         // 8 MB
__device__ __half g_expe[(size_t)BB * NN * NN];    // exp(e-8) fp16, masked->0 (67 MB)
__device__ float  g_pout[(size_t)SPLITK * BB * NN * FOUT];  // K-split partials (8 MB)

static __device__ __forceinline__ uint32_t smem_u32(const void* p) {
    return (uint32_t)__cvta_generic_to_shared(p);
}
static __device__ __forceinline__ void cp16(uint32_t dst, const void* src) {
    asm volatile("cp.async.cg.shared.global [%0], [%1], 16;" :: "r"(dst), "l"(src));
}
static __device__ __forceinline__ void cp_commit() {
    asm volatile("cp.async.commit_group;" ::: "memory");
}
template <int N>
static __device__ __forceinline__ void cp_wait() {
    asm volatile("cp.async.wait_group %0;" :: "n"(N) : "memory");
}

// exp(x - 8) on the FMA/ALU pipes (no MUFU). |rel err| ~4e-5.
static __device__ __forceinline__ float fast_exp_m8(float x) {
    const float y = fmaf(x, 1.4426950408889634f, -11.541560327111708f);
    const float z = y + 12582912.0f;
    const int   k = __float_as_int(z) - 0x4B400000;
    const float r = y - (z - 12582912.0f);
    float p = fmaf(r, 0.009618129107628f, 0.055504108664822f);
    p = fmaf(r, p, 0.240226506959101f);
    p = fmaf(r, p, 0.693147180559945f);
    p = fmaf(r, p, 1.0f);
    return __int_as_float(__float_as_int(p) + (k << 23));
}

// =====================================================================
// Kernel F: f1[r] = h[r,:] . (W@a1),  f2[r] = h[r,:] . (W@a2)
// Each block recomputes wa1/wa2 into smem (W is L2-resident; ~128 FMA/thr).
// warp per row slot (4 rows/warp); grid 512 x 256.
// =====================================================================
__global__ __launch_bounds__(256) void k_f12(const float* __restrict__ h,
                                             const float* __restrict__ W,
                                             const float* __restrict__ a)
{
    __shared__ float swa1[FIN];
    __shared__ float swa2[FIN];

    const int t = threadIdx.x;

    // per-block wa = W @ a  (t-th row of W, 64x2 FMAs)
    {
        float s1 = 0.f, s2 = 0.f;
#pragma unroll 8
        for (int o = 0; o < FOUT; ++o) {
            const float w = __ldg(&W[t * FOUT + o]);
            s1 = fmaf(w, __ldg(&a[o]), s1);
            s2 = fmaf(w, __ldg(&a[FOUT + o]), s2);
        }
        swa1[t] = s1;
        swa2[t] = s2;
    }
    __syncthreads();

    const int w = t >> 5;
    const int l = t & 31;

    const float4 wa1a = *(const float4*)&swa1[l * 4];
    const float4 wa1b = *(const float4*)&swa1[128 + l * 4];
    const float4 wa2a = *(const float4*)&swa2[l * 4];
    const float4 wa2b = *(const float4*)&swa2[128 + l * 4];

#pragma unroll
    for (int k = 0; k < 4; ++k) {
        const int r = blockIdx.x * 32 + w * 4 + k;
        const float4 h0 = *(const float4*)(h + (size_t)r * FIN + l * 4);
        const float4 h1 = *(const float4*)(h + (size_t)r * FIN + 128 + l * 4);
        float v1 = h0.x * wa1a.x;
        v1 = fmaf(h0.y, wa1a.y, v1); v1 = fmaf(h0.z, wa1a.z, v1); v1 = fmaf(h0.w, wa1a.w, v1);
        v1 = fmaf(h1.x, wa1b.x, v1); v1 = fmaf(h1.y, wa1b.y, v1);
        v1 = fmaf(h1.z, wa1b.z, v1); v1 = fmaf(h1.w, wa1b.w, v1);
        float v2 = h0.x * wa2a.x;
        v2 = fmaf(h0.y, wa2a.y, v2); v2 = fmaf(h0.z, wa2a.z, v2); v2 = fmaf(h0.w, wa2a.w, v2);
        v2 = fmaf(h1.x, wa2b.x, v2); v2 = fmaf(h1.y, wa2b.y, v2);
        v2 = fmaf(h1.z, wa2b.z, v2); v2 = fmaf(h1.w, wa2b.w, v2);
#pragma unroll
        for (int off = 16; off; off >>= 1) {
            v1 += __shfl_down_sync(0xffffffffu, v1, off);
            v2 += __shfl_down_sync(0xffffffffu, v2, off);
        }
        if (l == 0) { g_f1[r] = v1; g_f2[r] = v2; }
    }
}

// =====================================================================
// FUSED kernel: blocks [0, CS_BLOCKS) = colsum body (memory-bound);
// blocks [CS_BLOCKS, +PROJ_BLOCKS) = WhL projection body (compute-bound).
// =====================================================================
__global__ __launch_bounds__(256) void k_fused(const int* __restrict__ adj,
                                               const float* __restrict__ nt,
                                               const float* __restrict__ h,
                                               const float* __restrict__ W,
                                               const float* __restrict__ level)
{
    __shared__ float sh_h[32 * FIN];   // used by proj body only

    const int t = threadIdx.x;

    if (blockIdx.x < CS_BLOCKS) {
        // ================= colsum body =================
        const int cid = blockIdx.x;
        const int b = cid & 7;
        const int slice = cid >> 3;
        const int j = t * 8;
        const int i0 = slice * (NN / SPLIT);

        const float4 f2a = *(const float4*)(g_f2 + b * NN + j);
        const float4 f2b = *(const float4*)(g_f2 + b * NN + j + 4);

        // hoist the 16 f1 values for this block's rows into registers
        float f1v[NN / SPLIT];
#pragma unroll
        for (int k = 0; k < NN / SPLIT; ++k) f1v[k] = __ldg(&g_f1[b * NN + i0 + k]);

        size_t base = ((size_t)(b * NN + i0)) * NN + j;

        float s[8] = {0.f, 0.f, 0.f, 0.f, 0.f, 0.f, 0.f, 0.f};
#pragma unroll 8
        for (int ii = 0; ii < NN / SPLIT; ++ii) {
            const int4   av0 = __ldcs((const int4*)(adj + base));
            const int4   av1 = __ldcs((const int4*)(adj + base + 4));
            const float4 nt0 = __ldcs((const float4*)(nt + base));
            const float4 nt1 = __ldcs((const float4*)(nt + base + 4));
            const float  f1i = f1v[ii];

            const float x0 = f1i + f2a.x, x1 = f1i + f2a.y;
            const float x2 = f1i + f2a.z, x3 = f1i + f2a.w;
            const float x4 = f1i + f2b.x, x5 = f1i + f2b.y;
            const float x6 = f1i + f2b.z, x7 = f1i + f2b.w;

            const float p0 = av0.x > 0 ? fast_exp_m8((x0 > 0.f ? x0 : LALPHA * x0) * nt0.x) : 0.f;
            const float p1 = av0.y > 0 ? fast_exp_m8((x1 > 0.f ? x1 : LALPHA * x1) * nt0.y) : 0.f;
            const float p2 = av0.z > 0 ? fast_exp_m8((x2 > 0.f ? x2 : LALPHA * x2) * nt0.z) : 0.f;
            const float p3 = av0.w > 0 ? fast_exp_m8((x3 > 0.f ? x3 : LALPHA * x3) * nt0.w) : 0.f;
            const float p4 = av1.x > 0 ? fast_exp_m8((x4 > 0.f ? x4 : LALPHA * x4) * nt1.x) : 0.f;
            const float p5 = av1.y > 0 ? fast_exp_m8((x5 > 0.f ? x5 : LALPHA * x5) * nt1.y) : 0.f;
            const float p6 = av1.z > 0 ? fast_exp_m8((x6 > 0.f ? x6 : LALPHA * x6) * nt1.z) : 0.f;
            const float p7 = av1.w > 0 ? fast_exp_m8((x7 > 0.f ? x7 : LALPHA * x7) * nt1.w) : 0.f;

            const __half2 h0 = __floats2half2_rn(p0, p1);
            const __half2 h1 = __floats2half2_rn(p2, p3);
            const __half2 h2 = __floats2half2_rn(p4, p5);
            const __half2 h3 = __floats2half2_rn(p6, p7);
            uint4 st;
            st.x = *(const unsigned int*)&h0;
            st.y = *(const unsigned int*)&h1;
            st.z = *(const unsigned int*)&h2;
            st.w = *(const unsigned int*)&h3;
            *(uint4*)(g_expe + base) = st;

            s[0] += p0; s[1] += p1; s[2] += p2; s[3] += p3;
            s[4] += p4; s[5] += p5; s[6] += p6; s[7] += p7;
            base += NN;
        }
        float* pp = g_part + ((size_t)slice * BB + b) * NN + j;
        *(float4*)pp       = make_float4(s[0], s[1], s[2], s[3]);
        *(float4*)(pp + 4) = make_float4(s[4], s[5], s[6], s[7]);
    } else {
        // ================= WhL projection body ============
        const int row0 = (blockIdx.x - CS_BLOCKS) * 32;

        const float4* hg = (const float4*)(h + (size_t)row0 * FIN);
        float4* hs = (float4*)sh_h;
#pragma unroll
        for (int k = 0; k < 8; ++k) hs[t + k * 256] = hg[t + k * 256];
        __syncthreads();

        const int o = t & 63;
        const int g = t >> 6;

        float acc[8] = {0.f, 0.f, 0.f, 0.f, 0.f, 0.f, 0.f, 0.f};

#pragma unroll 4
        for (int f4 = 0; f4 < FIN / 4; ++f4) {
            const float w0 = __ldg(&W[(f4 * 4 + 0) * FOUT + o]);
            const float w1 = __ldg(&W[(f4 * 4 + 1) * FOUT + o]);
            const float w2 = __ldg(&W[(f4 * 4 + 2) * FOUT + o]);
            const float w3 = __ldg(&W[(f4 * 4 + 3) * FOUT + o]);
#pragma unroll
            for (int rr = 0; rr < 8; ++rr) {
                const float4 hv = *(const float4*)&sh_h[(g * 8 + rr) * FIN + f4 * 4];
                acc[rr] = fmaf(hv.x, w0, acc[rr]);
                acc[rr] = fmaf(hv.y, w1, acc[rr]);
                acc[rr] = fmaf(hv.z, w2, acc[rr]);
                acc[rr] = fmaf(hv.w, w3, acc[rr]);
            }
        }

#pragma unroll
        for (int rr = 0; rr < 8; ++rr) {
            const int row = row0 + g * 8 + rr;
            g_WhL[(size_t)row * FOUT + o] = acc[rr] * __ldg(&level[row]);
        }
    }
}

// =====================================================================
// Combine 128 partials -> inv; WhLh = fp16(WhL * inv).
// One column per thread in the reduction (128 independent coalesced
// loads => MLP ~128). grid 64 x 256.
// =====================================================================
__global__ __launch_bounds__(256) void k_comb()
{
    __shared__ float sinv[256];
    const int t = threadIdx.x;
    const int col0 = blockIdx.x * 256;
    const int col = col0 + t;

    float s = 0.f;
#pragma unroll 16
    for (int k = 0; k < SPLIT; ++k)
        s += g_part[(size_t)k * (BB * NN) + col];
    sinv[t] = 1.0f / s;
    __syncthreads();

    // scale 256 columns x 16 float4 = 4096 float4; 16 per thread, coalesced
#pragma unroll
    for (int k = 0; k < 16; ++k) {
        const int idx = k * 256 + t;
        const int cc = idx >> 4;
        const int o4 = idx & 15;
        const float inv = sinv[cc];
        const float4 v = ((const float4*)g_WhL)[(size_t)(col0 + cc) * 16 + o4];
        const __half2 h0 = __floats2half2_rn(v.x * inv, v.y * inv);
        const __half2 h1 = __floats2half2_rn(v.z * inv, v.w * inv);
        uint2 u;
        u.x = *(const unsigned int*)&h0;
        u.y = *(const unsigned int*)&h1;
        ((uint2*)g_WhLh)[(size_t)(col0 + cc) * 16 + o4] = u;
    }
}

// =====================================================================
// Kernel C: HMMA partial over a K-slice of 1024, ring-3 cp.async pipeline.
// grid (NN/64, BB, SPLITK) = 512 blocks x 256 threads.
// =====================================================================
#define PITCH 72
#define BUFH (64 * PITCH)

__global__ __launch_bounds__(256) void k_attn()
{
    __shared__ __half Ps[3][BUFH];
    __shared__ __half Ws[3][BUFH];

    const int t = threadIdx.x;
    const int lane = t & 31;
    const int warp = t >> 5;
    const int wr = warp >> 1;
    const int wc = warp & 1;
    const int b  = blockIdx.y;
    const int i0 = blockIdx.x * 64;
    const int ks = blockIdx.z;

    const int r0 = t >> 3, c0 = t & 7;
    const int r1 = r0 + 32;
    const __half* Pg = g_expe + ((size_t)(b * NN + i0)) * NN + ks * KSL;
    const __half* Wg = g_WhLh + ((size_t)(b * NN + ks * KSL)) * FOUT;

    const uint32_t dP0 = smem_u32(&Ps[0][r0 * PITCH + c0 * 8]);
    const uint32_t dP1 = smem_u32(&Ps[0][r1 * PITCH + c0 * 8]);
    const uint32_t dW0 = smem_u32(&Ws[0][r0 * PITCH + c0 * 8]);
    const uint32_t dW1 = smem_u32(&Ws[0][r1 * PITCH + c0 * 8]);
    const uint32_t bufStride = BUFH * sizeof(__half);

    float d[4][4];
#pragma unroll
    for (int n = 0; n < 4; ++n)
#pragma unroll
        for (int k = 0; k < 4; ++k) d[n][k] = 0.f;

    const uint32_t aBase = smem_u32(&Ps[0][(wr * 16 + (lane & 15)) * PITCH + (lane >> 4) * 8]);
    const uint32_t bBase = smem_u32(&Ws[0][(lane & 15) * PITCH + wc * 32 + (lane >> 4) * 8]);

#pragma unroll
    for (int pc = 0; pc < 2; ++pc) {
        const int k0 = pc * 64;
        const uint32_t nb = pc * bufStride;
        cp16(dP0 + nb, Pg + (size_t)r0 * NN + k0 + c0 * 8);
        cp16(dP1 + nb, Pg + (size_t)r1 * NN + k0 + c0 * 8);
        cp16(dW0 + nb, Wg + (size_t)(k0 + r0) * FOUT + c0 * 8);
        cp16(dW1 + nb, Wg + (size_t)(k0 + r1) * FOUT + c0 * 8);
        cp_commit();
    }

    int buf = 0;
    for (int ck = 0; ck < NCHUNK; ++ck) {
        if (ck + 1 < NCHUNK) cp_wait<1>(); else cp_wait<0>();
        __syncthreads();

        if (ck + 2 < NCHUNK) {
            const int k0 = (ck + 2) * 64;
            const int wbuf = (buf + 2 >= 3) ? buf - 1 : buf + 2;
            const uint32_t nb = wbuf * bufStride;
            cp16(dP0 + nb, Pg + (size_t)r0 * NN + k0 + c0 * 8);
            cp16(dP1 + nb, Pg + (size_t)r1 * NN + k0 + c0 * 8);
            cp16(dW0 + nb, Wg + (size_t)(k0 + r0) * FOUT + c0 * 8);
            cp16(dW1 + nb, Wg + (size_t)(k0 + r1) * FOUT + c0 * 8);
            cp_commit();
        }

        const uint32_t aB = aBase + buf * bufStride;
        const uint32_t bB = bBase + buf * bufStride;
#pragma unroll
        for (int kss = 0; kss < 4; ++kss) {
            uint32_t a0, a1, a2, a3;
            asm volatile("ldmatrix.sync.aligned.m8n8.x4.shared.b16 {%0,%1,%2,%3}, [%4];"
                         : "=r"(a0), "=r"(a1), "=r"(a2), "=r"(a3)
                         : "r"(aB + kss * 16 * 2));
#pragma unroll
            for (int np = 0; np < 2; ++np) {
                uint32_t b0, b1, b2, b3;
                asm volatile("ldmatrix.sync.aligned.m8n8.x4.trans.shared.b16 {%0,%1,%2,%3}, [%4];"
                             : "=r"(b0), "=r"(b1), "=r"(b2), "=r"(b3)
                             : "r"(bB + (kss * 16 * PITCH + np * 16) * 2));
                asm volatile("mma.sync.aligned.m16n8k16.row.col.f32.f16.f16.f32 "
                             "{%0,%1,%2,%3}, {%4,%5,%6,%7}, {%8,%9}, {%0,%1,%2,%3};"
                             : "+f"(d[np*2][0]), "+f"(d[np*2][1]), "+f"(d[np*2][2]), "+f"(d[np*2][3])
                             : "r"(a0), "r"(a1), "r"(a2), "r"(a3), "r"(b0), "r"(b1));
                asm volatile("mma.sync.aligned.m16n8k16.row.col.f32.f16.f16.f32 "
                             "{%0,%1,%2,%3}, {%4,%5,%6,%7}, {%8,%9}, {%0,%1,%2,%3};"
                             : "+f"(d[np*2+1][0]), "+f"(d[np*2+1][1]), "+f"(d[np*2+1][2]), "+f"(d[np*2+1][3])
                             : "r"(a0), "r"(a1), "r"(a2), "r"(a3), "r"(b2), "r"(b3));
            }
        }

        buf = (buf + 1 >= 3) ? 0 : buf + 1;
    }

    const int orow = i0 + wr * 16 + (lane >> 2);
    const int ocol = wc * 32 + (lane & 3) * 2;
    float* obase = g_pout + (((size_t)ks * BB + b) * NN + orow) * FOUT + ocol;
#pragma unroll
    for (int nt4 = 0; nt4 < 4; ++nt4) {
        *(float2*)(obase + nt4 * 8) = make_float2(d[nt4][0], d[nt4][1]);
        *(float2*)(obase + (size_t)8 * FOUT + nt4 * 8) = make_float2(d[nt4][2], d[nt4][3]);
    }
}

// =====================================================================
// Combine K-split partials + relu -> out
// =====================================================================
__global__ __launch_bounds__(256) void k_out(float* __restrict__ out)
{
    const int i4 = blockIdx.x * 256 + threadIdx.x;
    const size_t stride4 = (size_t)BB * NN * FOUT / 4;
    float4 s = ((const float4*)g_pout)[i4];
#pragma unroll
    for (int k = 1; k < SPLITK; ++k) {
        const float4 v = ((const float4*)g_pout)[k * stride4 + i4];
        s.x += v.x; s.y += v.y; s.z += v.z; s.w += v.w;
    }
    s.x = fmaxf(s.x, 0.f); s.y = fmaxf(s.y, 0.f);
    s.z = fmaxf(s.z, 0.f); s.w = fmaxf(s.w, 0.f);
    ((float4*)out)[i4] = s;
}

// =====================================================================
extern "C" void kernel_launch(void* const* d_in, const int* in_sizes, int n_in,
                              void* d_out, int out_size)
{
    const float* h     = (const float*)d_in[0];
    const int*   adj   = (const int*)  d_in[1];
    const float* level = (const float*)d_in[2];
    const float* nt    = (const float*)d_in[3];
    const float* W     = (const float*)d_in[4];
    const float* a     = (const float*)d_in[5];
    float* out = (float*)d_out;

    k_f12<<<(BB * NN) / 32, 256>>>(h, W, a);
    k_fused<<<CS_BLOCKS + PROJ_BLOCKS, 256>>>(adj, nt, h, W, level);
    k_comb<<<(BB * NN) / 256, 256>>>();
    dim3 ga(NN / 64, BB, SPLITK);
    k_attn<<<ga, 256>>>();
    k_out<<<(BB * NN * FOUT / 4) / 256, 256>>>(out);
}

// round 16
// speedup vs baseline: 1.2231x; 1.2231x over previous
#include <cuda_runtime.h>
#include <cuda_fp16.h>
#include <cstdint>

#define BB 8
#define NN 2048
#define FIN 256
#define FOUT 64
#define LALPHA 0.2f
#define SPLIT 128
#define SPLITK 2
#define KSL (NN / SPLITK)
#define NCHUNK (KSL / 64)
#define CS_BLOCKS (BB * SPLIT)          // 1024 colsum blocks
#define PROJ_BLOCKS ((BB * NN) / 32)    // 512 projection blocks

// ---- scratch (device globals; no allocation) ----
__device__ float  g_WhL[BB * NN * FOUT];           // Wh*level fp32 (4 MB)
__device__ __half g_WhLh[BB * NN * FOUT];          // scaled fp16 (2 MB)
__device__ float  g_f1[BB * NN];
__device__ float  g_f2[BB * NN];
__device__ float  g_wa1[FIN];
__device__ float  g_wa2[FIN];
__device__ float  g_part[SPLIT * BB * NN];         // 8 MB
__device__ __half g_expe[(size_t)BB * NN * NN];    // exp(e-8) fp16, masked->0 (67 MB)
__device__ float  g_pout[(size_t)SPLITK * BB * NN * FOUT];  // K-split partials (8 MB)

static __device__ __forceinline__ uint32_t smem_u32(const void* p) {
    return (uint32_t)__cvta_generic_to_shared(p);
}
static __device__ __forceinline__ void cp16(uint32_t dst, const void* src) {
    asm volatile("cp.async.cg.shared.global [%0], [%1], 16;" :: "r"(dst), "l"(src));
}
static __device__ __forceinline__ void cp_commit() {
    asm volatile("cp.async.commit_group;" ::: "memory");
}
template <int N>
static __device__ __forceinline__ void cp_wait() {
    asm volatile("cp.async.wait_group %0;" :: "n"(N) : "memory");
}

// exp(x - 8) on the FMA/ALU pipes (no MUFU). |rel err| ~4e-5.
static __device__ __forceinline__ float fast_exp_m8(float x) {
    const float y = fmaf(x, 1.4426950408889634f, -11.541560327111708f);
    const float z = y + 12582912.0f;
    const int   k = __float_as_int(z) - 0x4B400000;
    const float r = y - (z - 12582912.0f);
    float p = fmaf(r, 0.009618129107628f, 0.055504108664822f);
    p = fmaf(r, p, 0.240226506959101f);
    p = fmaf(r, p, 0.693147180559945f);
    p = fmaf(r, p, 1.0f);
    return __int_as_float(__float_as_int(p) + (k << 23));
}

// =====================================================================
// Kernel W: wa1 = W @ a1, wa2 = W @ a2  (256 threads, 1 block)
// =====================================================================
__global__ void k_wa(const float* __restrict__ W, const float* __restrict__ a)
{
    const int f = threadIdx.x;
    float s1 = 0.f, s2 = 0.f;
#pragma unroll 8
    for (int o = 0; o < FOUT; ++o) {
        const float w = __ldg(&W[f * FOUT + o]);
        s1 = fmaf(w, __ldg(&a[o]), s1);
        s2 = fmaf(w, __ldg(&a[FOUT + o]), s2);
    }
    g_wa1[f] = s1;
    g_wa2[f] = s2;
}

// =====================================================================
// Kernel F: f1[r] = h[r,:] . wa1,  f2[r] = h[r,:] . wa2
// warp per row (4 rows/warp); grid 512 x 256.
// =====================================================================
__global__ __launch_bounds__(256) void k_f12(const float* __restrict__ h)
{
    const int w = threadIdx.x >> 5;
    const int l = threadIdx.x & 31;

    const float4 wa1a = *(const float4*)&g_wa1[l * 4];
    const float4 wa1b = *(const float4*)&g_wa1[128 + l * 4];
    const float4 wa2a = *(const float4*)&g_wa2[l * 4];
    const float4 wa2b = *(const float4*)&g_wa2[128 + l * 4];

#pragma unroll
    for (int k = 0; k < 4; ++k) {
        const int r = blockIdx.x * 32 + w * 4 + k;
        const float4 h0 = *(const float4*)(h + (size_t)r * FIN + l * 4);
        const float4 h1 = *(const float4*)(h + (size_t)r * FIN + 128 + l * 4);
        float v1 = h0.x * wa1a.x;
        v1 = fmaf(h0.y, wa1a.y, v1); v1 = fmaf(h0.z, wa1a.z, v1); v1 = fmaf(h0.w, wa1a.w, v1);
        v1 = fmaf(h1.x, wa1b.x, v1); v1 = fmaf(h1.y, wa1b.y, v1);
        v1 = fmaf(h1.z, wa1b.z, v1); v1 = fmaf(h1.w, wa1b.w, v1);
        float v2 = h0.x * wa2a.x;
        v2 = fmaf(h0.y, wa2a.y, v2); v2 = fmaf(h0.z, wa2a.z, v2); v2 = fmaf(h0.w, wa2a.w, v2);
        v2 = fmaf(h1.x, wa2b.x, v2); v2 = fmaf(h1.y, wa2b.y, v2);
        v2 = fmaf(h1.z, wa2b.z, v2); v2 = fmaf(h1.w, wa2b.w, v2);
#pragma unroll
        for (int off = 16; off; off >>= 1) {
            v1 += __shfl_down_sync(0xffffffffu, v1, off);
            v2 += __shfl_down_sync(0xffffffffu, v2, off);
        }
        if (l == 0) { g_f1[r] = v1; g_f2[r] = v2; }
    }
}

// =====================================================================
// FUSED kernel: blocks [0, CS_BLOCKS) = colsum body (memory-bound);
// blocks [CS_BLOCKS, +PROJ_BLOCKS) = WhL projection body (compute-bound).
// =====================================================================
__global__ __launch_bounds__(256) void k_fused(const int* __restrict__ adj,
                                               const float* __restrict__ nt,
                                               const float* __restrict__ h,
                                               const float* __restrict__ W,
                                               const float* __restrict__ level)
{
    __shared__ float sh_h[32 * FIN];   // used by proj body only

    const int t = threadIdx.x;

    if (blockIdx.x < CS_BLOCKS) {
        // ================= colsum body (R12/R13 proven) =================
        const int cid = blockIdx.x;
        const int b = cid & 7;
        const int slice = cid >> 3;
        const int j = t * 8;
        const int i0 = slice * (NN / SPLIT);

        const float4 f2a = *(const float4*)(g_f2 + b * NN + j);
        const float4 f2b = *(const float4*)(g_f2 + b * NN + j + 4);
        const float* f1p = g_f1 + b * NN + i0;
        size_t base = ((size_t)(b * NN + i0)) * NN + j;

        float s[8] = {0.f, 0.f, 0.f, 0.f, 0.f, 0.f, 0.f, 0.f};
#pragma unroll 4
        for (int ii = 0; ii < NN / SPLIT; ++ii) {
            const int4   av0 = __ldcs((const int4*)(adj + base));
            const int4   av1 = __ldcs((const int4*)(adj + base + 4));
            const float4 nt0 = __ldcs((const float4*)(nt + base));
            const float4 nt1 = __ldcs((const float4*)(nt + base + 4));
            const float  f1i = __ldg(&f1p[ii]);

            const float x0 = f1i + f2a.x, x1 = f1i + f2a.y;
            const float x2 = f1i + f2a.z, x3 = f1i + f2a.w;
            const float x4 = f1i + f2b.x, x5 = f1i + f2b.y;
            const float x6 = f1i + f2b.z, x7 = f1i + f2b.w;

            const float p0 = av0.x > 0 ? fast_exp_m8((x0 > 0.f ? x0 : LALPHA * x0) * nt0.x) : 0.f;
            const float p1 = av0.y > 0 ? fast_exp_m8((x1 > 0.f ? x1 : LALPHA * x1) * nt0.y) : 0.f;
            const float p2 = av0.z > 0 ? fast_exp_m8((x2 > 0.f ? x2 : LALPHA * x2) * nt0.z) : 0.f;
            const float p3 = av0.w > 0 ? fast_exp_m8((x3 > 0.f ? x3 : LALPHA * x3) * nt0.w) : 0.f;
            const float p4 = av1.x > 0 ? fast_exp_m8((x4 > 0.f ? x4 : LALPHA * x4) * nt1.x) : 0.f;
            const float p5 = av1.y > 0 ? fast_exp_m8((x5 > 0.f ? x5 : LALPHA * x5) * nt1.y) : 0.f;
            const float p6 = av1.z > 0 ? fast_exp_m8((x6 > 0.f ? x6 : LALPHA * x6) * nt1.z) : 0.f;
            const float p7 = av1.w > 0 ? fast_exp_m8((x7 > 0.f ? x7 : LALPHA * x7) * nt1.w) : 0.f;

            const __half2 h0 = __floats2half2_rn(p0, p1);
            const __half2 h1 = __floats2half2_rn(p2, p3);
            const __half2 h2 = __floats2half2_rn(p4, p5);
            const __half2 h3 = __floats2half2_rn(p6, p7);
            uint4 st;
            st.x = *(const unsigned int*)&h0;
            st.y = *(const unsigned int*)&h1;
            st.z = *(const unsigned int*)&h2;
            st.w = *(const unsigned int*)&h3;
            *(uint4*)(g_expe + base) = st;

            s[0] += p0; s[1] += p1; s[2] += p2; s[3] += p3;
            s[4] += p4; s[5] += p5; s[6] += p6; s[7] += p7;
            base += NN;
        }
        float* pp = g_part + ((size_t)slice * BB + b) * NN + j;
        *(float4*)pp       = make_float4(s[0], s[1], s[2], s[3]);
        *(float4*)(pp + 4) = make_float4(s[4], s[5], s[6], s[7]);
    } else {
        // ================= WhL projection body ============
        const int row0 = (blockIdx.x - CS_BLOCKS) * 32;

        const float4* hg = (const float4*)(h + (size_t)row0 * FIN);
        float4* hs = (float4*)sh_h;
#pragma unroll
        for (int k = 0; k < 8; ++k) hs[t + k * 256] = hg[t + k * 256];
        __syncthreads();

        const int o = t & 63;
        const int g = t >> 6;

        float acc[8] = {0.f, 0.f, 0.f, 0.f, 0.f, 0.f, 0.f, 0.f};

#pragma unroll 4
        for (int f4 = 0; f4 < FIN / 4; ++f4) {
            const float w0 = __ldg(&W[(f4 * 4 + 0) * FOUT + o]);
            const float w1 = __ldg(&W[(f4 * 4 + 1) * FOUT + o]);
            const float w2 = __ldg(&W[(f4 * 4 + 2) * FOUT + o]);
            const float w3 = __ldg(&W[(f4 * 4 + 3) * FOUT + o]);
#pragma unroll
            for (int rr = 0; rr < 8; ++rr) {
                const float4 hv = *(const float4*)&sh_h[(g * 8 + rr) * FIN + f4 * 4];
                acc[rr] = fmaf(hv.x, w0, acc[rr]);
                acc[rr] = fmaf(hv.y, w1, acc[rr]);
                acc[rr] = fmaf(hv.z, w2, acc[rr]);
                acc[rr] = fmaf(hv.w, w3, acc[rr]);
            }
        }

#pragma unroll
        for (int rr = 0; rr < 8; ++rr) {
            const int row = row0 + g * 8 + rr;
            g_WhL[(size_t)row * FOUT + o] = acc[rr] * __ldg(&level[row]);
        }
    }
}

// =====================================================================
// Combine 128 partials -> inv; WhLh = fp16(WhL * inv).
// One column per thread in the reduction (128 independent coalesced
// loads => MLP ~128). grid 64 x 256.
// =====================================================================
__global__ __launch_bounds__(256) void k_comb()
{
    __shared__ float sinv[256];
    const int t = threadIdx.x;
    const int col0 = blockIdx.x * 256;
    const int col = col0 + t;

    float s = 0.f;
#pragma unroll 16
    for (int k = 0; k < SPLIT; ++k)
        s += g_part[(size_t)k * (BB * NN) + col];
    sinv[t] = 1.0f / s;
    __syncthreads();

    // scale 256 columns x 16 float4 = 4096 float4; 16 per thread, coalesced
#pragma unroll
    for (int k = 0; k < 16; ++k) {
        const int idx = k * 256 + t;
        const int cc = idx >> 4;
        const int o4 = idx & 15;
        const float inv = sinv[cc];
        const float4 v = ((const float4*)g_WhL)[(size_t)(col0 + cc) * 16 + o4];
        const __half2 h0 = __floats2half2_rn(v.x * inv, v.y * inv);
        const __half2 h1 = __floats2half2_rn(v.z * inv, v.w * inv);
        uint2 u;
        u.x = *(const unsigned int*)&h0;
        u.y = *(const unsigned int*)&h1;
        ((uint2*)g_WhLh)[(size_t)(col0 + cc) * 16 + o4] = u;
    }
}

// =====================================================================
// Kernel C: HMMA partial over a K-slice of 1024, ring-3 cp.async pipeline.
// grid (NN/64, BB, SPLITK) = 512 blocks x 256 threads.
// =====================================================================
#define PITCH 72
#define BUFH (64 * PITCH)

__global__ __launch_bounds__(256) void k_attn()
{
    __shared__ __half Ps[3][BUFH];
    __shared__ __half Ws[3][BUFH];

    const int t = threadIdx.x;
    const int lane = t & 31;
    const int warp = t >> 5;
    const int wr = warp >> 1;
    const int wc = warp & 1;
    const int b  = blockIdx.y;
    const int i0 = blockIdx.x * 64;
    const int ks = blockIdx.z;

    const int r0 = t >> 3, c0 = t & 7;
    const int r1 = r0 + 32;
    const __half* Pg = g_expe + ((size_t)(b * NN + i0)) * NN + ks * KSL;
    const __half* Wg = g_WhLh + ((size_t)(b * NN + ks * KSL)) * FOUT;

    const uint32_t dP0 = smem_u32(&Ps[0][r0 * PITCH + c0 * 8]);
    const uint32_t dP1 = smem_u32(&Ps[0][r1 * PITCH + c0 * 8]);
    const uint32_t dW0 = smem_u32(&Ws[0][r0 * PITCH + c0 * 8]);
    const uint32_t dW1 = smem_u32(&Ws[0][r1 * PITCH + c0 * 8]);
    const uint32_t bufStride = BUFH * sizeof(__half);

    float d[4][4];
#pragma unroll
    for (int n = 0; n < 4; ++n)
#pragma unroll
        for (int k = 0; k < 4; ++k) d[n][k] = 0.f;

    const uint32_t aBase = smem_u32(&Ps[0][(wr * 16 + (lane & 15)) * PITCH + (lane >> 4) * 8]);
    const uint32_t bBase = smem_u32(&Ws[0][(lane & 15) * PITCH + wc * 32 + (lane >> 4) * 8]);

#pragma unroll
    for (int pc = 0; pc < 2; ++pc) {
        const int k0 = pc * 64;
        const uint32_t nb = pc * bufStride;
        cp16(dP0 + nb, Pg + (size_t)r0 * NN + k0 + c0 * 8);
        cp16(dP1 + nb, Pg + (size_t)r1 * NN + k0 + c0 * 8);
        cp16(dW0 + nb, Wg + (size_t)(k0 + r0) * FOUT + c0 * 8);
        cp16(dW1 + nb, Wg + (size_t)(k0 + r1) * FOUT + c0 * 8);
        cp_commit();
    }

    int buf = 0;
    for (int ck = 0; ck < NCHUNK; ++ck) {
        if (ck + 1 < NCHUNK) cp_wait<1>(); else cp_wait<0>();
        __syncthreads();

        if (ck + 2 < NCHUNK) {
            const int k0 = (ck + 2) * 64;
            const int wbuf = (buf + 2 >= 3) ? buf - 1 : buf + 2;
            const uint32_t nb = wbuf * bufStride;
            cp16(dP0 + nb, Pg + (size_t)r0 * NN + k0 + c0 * 8);
            cp16(dP1 + nb, Pg + (size_t)r1 * NN + k0 + c0 * 8);
            cp16(dW0 + nb, Wg + (size_t)(k0 + r0) * FOUT + c0 * 8);
            cp16(dW1 + nb, Wg + (size_t)(k0 + r1) * FOUT + c0 * 8);
            cp_commit();
        }

        const uint32_t aB = aBase + buf * bufStride;
        const uint32_t bB = bBase + buf * bufStride;
#pragma unroll
        for (int kss = 0; kss < 4; ++kss) {
            uint32_t a0, a1, a2, a3;
            asm volatile("ldmatrix.sync.aligned.m8n8.x4.shared.b16 {%0,%1,%2,%3}, [%4];"
                         : "=r"(a0), "=r"(a1), "=r"(a2), "=r"(a3)
                         : "r"(aB + kss * 16 * 2));
#pragma unroll
            for (int np = 0; np < 2; ++np) {
                uint32_t b0, b1, b2, b3;
                asm volatile("ldmatrix.sync.aligned.m8n8.x4.trans.shared.b16 {%0,%1,%2,%3}, [%4];"
                             : "=r"(b0), "=r"(b1), "=r"(b2), "=r"(b3)
                             : "r"(bB + (kss * 16 * PITCH + np * 16) * 2));
                asm volatile("mma.sync.aligned.m16n8k16.row.col.f32.f16.f16.f32 "
                             "{%0,%1,%2,%3}, {%4,%5,%6,%7}, {%8,%9}, {%0,%1,%2,%3};"
                             : "+f"(d[np*2][0]), "+f"(d[np*2][1]), "+f"(d[np*2][2]), "+f"(d[np*2][3])
                             : "r"(a0), "r"(a1), "r"(a2), "r"(a3), "r"(b0), "r"(b1));
                asm volatile("mma.sync.aligned.m16n8k16.row.col.f32.f16.f16.f32 "
                             "{%0,%1,%2,%3}, {%4,%5,%6,%7}, {%8,%9}, {%0,%1,%2,%3};"
                             : "+f"(d[np*2+1][0]), "+f"(d[np*2+1][1]), "+f"(d[np*2+1][2]), "+f"(d[np*2+1][3])
                             : "r"(a0), "r"(a1), "r"(a2), "r"(a3), "r"(b2), "r"(b3));
            }
        }

        buf = (buf + 1 >= 3) ? 0 : buf + 1;
    }

    const int orow = i0 + wr * 16 + (lane >> 2);
    const int ocol = wc * 32 + (lane & 3) * 2;
    float* obase = g_pout + (((size_t)ks * BB + b) * NN + orow) * FOUT + ocol;
#pragma unroll
    for (int nt4 = 0; nt4 < 4; ++nt4) {
        *(float2*)(obase + nt4 * 8) = make_float2(d[nt4][0], d[nt4][1]);
        *(float2*)(obase + (size_t)8 * FOUT + nt4 * 8) = make_float2(d[nt4][2], d[nt4][3]);
    }
}

// =====================================================================
// Combine K-split partials + relu -> out
// =====================================================================
__global__ __launch_bounds__(256) void k_out(float* __restrict__ out)
{
    const int i4 = blockIdx.x * 256 + threadIdx.x;
    const size_t stride4 = (size_t)BB * NN * FOUT / 4;
    float4 s = ((const float4*)g_pout)[i4];
#pragma unroll
    for (int k = 1; k < SPLITK; ++k) {
        const float4 v = ((const float4*)g_pout)[k * stride4 + i4];
        s.x += v.x; s.y += v.y; s.z += v.z; s.w += v.w;
    }
    s.x = fmaxf(s.x, 0.f); s.y = fmaxf(s.y, 0.f);
    s.z = fmaxf(s.z, 0.f); s.w = fmaxf(s.w, 0.f);
    ((float4*)out)[i4] = s;
}

// =====================================================================
extern "C" void kernel_launch(void* const* d_in, const int* in_sizes, int n_in,
                              void* d_out, int out_size)
{
    const float* h     = (const float*)d_in[0];
    const int*   adj   = (const int*)  d_in[1];
    const float* level = (const float*)d_in[2];
    const float* nt    = (const float*)d_in[3];
    const float* W     = (const float*)d_in[4];
    const float* a     = (const float*)d_in[5];
    float* out = (float*)d_out;

    k_wa<<<1, 256>>>(W, a);
    k_f12<<<(BB * NN) / 32, 256>>>(h);
    k_fused<<<CS_BLOCKS + PROJ_BLOCKS, 256>>>(adj, nt, h, W, level);
    k_comb<<<(BB * NN) / 256, 256>>>();
    dim3 ga(NN / 64, BB, SPLITK);
    k_attn<<<ga, 256>>>();
    k_out<<<(BB * NN * FOUT / 4) / 256, 256>>>(out);
}

// round 17
// speedup vs baseline: 1.2998x; 1.0627x over previous
#include <cuda_runtime.h>
#include <cuda_fp16.h>
#include <cstdint>

#define BB 8
#define NN 2048
#define FIN 256
#define FOUT 64
#define LALPHA 0.2f
#define SPLIT 128
#define SPLITK 4
#define KSL (NN / SPLITK)
#define NCHUNK (KSL / 64)
#define CS_BLOCKS (BB * SPLIT)          // 1024 colsum blocks
#define PROJ_BLOCKS ((BB * NN) / 32)    // 512 projection blocks

// ---- scratch (device globals; no allocation) ----
__device__ float  g_WhL[BB * NN * FOUT];           // Wh*level fp32 (4 MB)
__device__ __half g_WhLh[BB * NN * FOUT];          // scaled fp16 (2 MB)
__device__ float  g_f1[BB * NN];
__device__ float  g_f2[BB * NN];
__device__ float  g_wa1[FIN];
__device__ float  g_wa2[FIN];
__device__ float  g_part[SPLIT * BB * NN];         // 8 MB
__device__ __half g_expe[(size_t)BB * NN * NN];    // exp(e-8) fp16, masked->0 (67 MB)
__device__ float  g_pout[(size_t)SPLITK * BB * NN * FOUT];  // K-split partials (16 MB)

static __device__ __forceinline__ uint32_t smem_u32(const void* p) {
    return (uint32_t)__cvta_generic_to_shared(p);
}
static __device__ __forceinline__ void cp16(uint32_t dst, const void* src) {
    asm volatile("cp.async.cg.shared.global [%0], [%1], 16;" :: "r"(dst), "l"(src));
}
static __device__ __forceinline__ void cp_commit() {
    asm volatile("cp.async.commit_group;" ::: "memory");
}
template <int N>
static __device__ __forceinline__ void cp_wait() {
    asm volatile("cp.async.wait_group %0;" :: "n"(N) : "memory");
}

// exp(x - 8) on the FMA/ALU pipes (no MUFU). |rel err| ~4e-5.
static __device__ __forceinline__ float fast_exp_m8(float x) {
    const float y = fmaf(x, 1.4426950408889634f, -11.541560327111708f);
    const float z = y + 12582912.0f;
    const int   k = __float_as_int(z) - 0x4B400000;
    const float r = y - (z - 12582912.0f);
    float p = fmaf(r, 0.009618129107628f, 0.055504108664822f);
    p = fmaf(r, p, 0.240226506959101f);
    p = fmaf(r, p, 0.693147180559945f);
    p = fmaf(r, p, 1.0f);
    return __int_as_float(__float_as_int(p) + (k << 23));
}

// =====================================================================
// Kernel W: wa1 = W @ a1, wa2 = W @ a2  (256 threads, 1 block)
// =====================================================================
__global__ void k_wa(const float* __restrict__ W, const float* __restrict__ a)
{
    const int f = threadIdx.x;
    float s1 = 0.f, s2 = 0.f;
#pragma unroll 8
    for (int o = 0; o < FOUT; ++o) {
        const float w = __ldg(&W[f * FOUT + o]);
        s1 = fmaf(w, __ldg(&a[o]), s1);
        s2 = fmaf(w, __ldg(&a[FOUT + o]), s2);
    }
    g_wa1[f] = s1;
    g_wa2[f] = s2;
}

// =====================================================================
// Kernel F: f1[r] = h[r,:] . wa1,  f2[r] = h[r,:] . wa2
// warp per row (4 rows/warp); grid 512 x 256.
// =====================================================================
__global__ __launch_bounds__(256) void k_f12(const float* __restrict__ h)
{
    const int w = threadIdx.x >> 5;
    const int l = threadIdx.x & 31;

    const float4 wa1a = *(const float4*)&g_wa1[l * 4];
    const float4 wa1b = *(const float4*)&g_wa1[128 + l * 4];
    const float4 wa2a = *(const float4*)&g_wa2[l * 4];
    const float4 wa2b = *(const float4*)&g_wa2[128 + l * 4];

#pragma unroll
    for (int k = 0; k < 4; ++k) {
        const int r = blockIdx.x * 32 + w * 4 + k;
        const float4 h0 = *(const float4*)(h + (size_t)r * FIN + l * 4);
        const float4 h1 = *(const float4*)(h + (size_t)r * FIN + 128 + l * 4);
        float v1 = h0.x * wa1a.x;
        v1 = fmaf(h0.y, wa1a.y, v1); v1 = fmaf(h0.z, wa1a.z, v1); v1 = fmaf(h0.w, wa1a.w, v1);
        v1 = fmaf(h1.x, wa1b.x, v1); v1 = fmaf(h1.y, wa1b.y, v1);
        v1 = fmaf(h1.z, wa1b.z, v1); v1 = fmaf(h1.w, wa1b.w, v1);
        float v2 = h0.x * wa2a.x;
        v2 = fmaf(h0.y, wa2a.y, v2); v2 = fmaf(h0.z, wa2a.z, v2); v2 = fmaf(h0.w, wa2a.w, v2);
        v2 = fmaf(h1.x, wa2b.x, v2); v2 = fmaf(h1.y, wa2b.y, v2);
        v2 = fmaf(h1.z, wa2b.z, v2); v2 = fmaf(h1.w, wa2b.w, v2);
#pragma unroll
        for (int off = 16; off; off >>= 1) {
            v1 += __shfl_down_sync(0xffffffffu, v1, off);
            v2 += __shfl_down_sync(0xffffffffu, v2, off);
        }
        if (l == 0) { g_f1[r] = v1; g_f2[r] = v2; }
    }
}

// =====================================================================
// FUSED kernel: blocks [0, CS_BLOCKS) = colsum body (memory-bound);
// blocks [CS_BLOCKS, +PROJ_BLOCKS) = WhL projection body (compute-bound).
// =====================================================================
__global__ __launch_bounds__(256) void k_fused(const int* __restrict__ adj,
                                               const float* __restrict__ nt,
                                               const float* __restrict__ h,
                                               const float* __restrict__ W,
                                               const float* __restrict__ level)
{
    __shared__ float sh_h[32 * FIN];   // used by proj body only

    const int t = threadIdx.x;

    if (blockIdx.x < CS_BLOCKS) {
        // ================= colsum body (R12/R13 proven) =================
        const int cid = blockIdx.x;
        const int b = cid & 7;
        const int slice = cid >> 3;
        const int j = t * 8;
        const int i0 = slice * (NN / SPLIT);

        const float4 f2a = *(const float4*)(g_f2 + b * NN + j);
        const float4 f2b = *(const float4*)(g_f2 + b * NN + j + 4);
        const float* f1p = g_f1 + b * NN + i0;
        size_t base = ((size_t)(b * NN + i0)) * NN + j;

        float s[8] = {0.f, 0.f, 0.f, 0.f, 0.f, 0.f, 0.f, 0.f};
#pragma unroll 4
        for (int ii = 0; ii < NN / SPLIT; ++ii) {
            const int4   av0 = __ldcs((const int4*)(adj + base));
            const int4   av1 = __ldcs((const int4*)(adj + base + 4));
            const float4 nt0 = __ldcs((const float4*)(nt + base));
            const float4 nt1 = __ldcs((const float4*)(nt + base + 4));
            const float  f1i = __ldg(&f1p[ii]);

            const float x0 = f1i + f2a.x, x1 = f1i + f2a.y;
            const float x2 = f1i + f2a.z, x3 = f1i + f2a.w;
            const float x4 = f1i + f2b.x, x5 = f1i + f2b.y;
            const float x6 = f1i + f2b.z, x7 = f1i + f2b.w;

            const float p0 = av0.x > 0 ? fast_exp_m8((x0 > 0.f ? x0 : LALPHA * x0) * nt0.x) : 0.f;
            const float p1 = av0.y > 0 ? fast_exp_m8((x1 > 0.f ? x1 : LALPHA * x1) * nt0.y) : 0.f;
            const float p2 = av0.z > 0 ? fast_exp_m8((x2 > 0.f ? x2 : LALPHA * x2) * nt0.z) : 0.f;
            const float p3 = av0.w > 0 ? fast_exp_m8((x3 > 0.f ? x3 : LALPHA * x3) * nt0.w) : 0.f;
            const float p4 = av1.x > 0 ? fast_exp_m8((x4 > 0.f ? x4 : LALPHA * x4) * nt1.x) : 0.f;
            const float p5 = av1.y > 0 ? fast_exp_m8((x5 > 0.f ? x5 : LALPHA * x5) * nt1.y) : 0.f;
            const float p6 = av1.z > 0 ? fast_exp_m8((x6 > 0.f ? x6 : LALPHA * x6) * nt1.z) : 0.f;
            const float p7 = av1.w > 0 ? fast_exp_m8((x7 > 0.f ? x7 : LALPHA * x7) * nt1.w) : 0.f;

            const __half2 h0 = __floats2half2_rn(p0, p1);
            const __half2 h1 = __floats2half2_rn(p2, p3);
            const __half2 h2 = __floats2half2_rn(p4, p5);
            const __half2 h3 = __floats2half2_rn(p6, p7);
            uint4 st;
            st.x = *(const unsigned int*)&h0;
            st.y = *(const unsigned int*)&h1;
            st.z = *(const unsigned int*)&h2;
            st.w = *(const unsigned int*)&h3;
            *(uint4*)(g_expe + base) = st;

            s[0] += p0; s[1] += p1; s[2] += p2; s[3] += p3;
            s[4] += p4; s[5] += p5; s[6] += p6; s[7] += p7;
            base += NN;
        }
        float* pp = g_part + ((size_t)slice * BB + b) * NN + j;
        *(float4*)pp       = make_float4(s[0], s[1], s[2], s[3]);
        *(float4*)(pp + 4) = make_float4(s[4], s[5], s[6], s[7]);
    } else {
        // ================= WhL projection body ============
        const int row0 = (blockIdx.x - CS_BLOCKS) * 32;

        const float4* hg = (const float4*)(h + (size_t)row0 * FIN);
        float4* hs = (float4*)sh_h;
#pragma unroll
        for (int k = 0; k < 8; ++k) hs[t + k * 256] = hg[t + k * 256];
        __syncthreads();

        const int o = t & 63;
        const int g = t >> 6;

        float acc[8] = {0.f, 0.f, 0.f, 0.f, 0.f, 0.f, 0.f, 0.f};

#pragma unroll 4
        for (int f4 = 0; f4 < FIN / 4; ++f4) {
            const float w0 = __ldg(&W[(f4 * 4 + 0) * FOUT + o]);
            const float w1 = __ldg(&W[(f4 * 4 + 1) * FOUT + o]);
            const float w2 = __ldg(&W[(f4 * 4 + 2) * FOUT + o]);
            const float w3 = __ldg(&W[(f4 * 4 + 3) * FOUT + o]);
#pragma unroll
            for (int rr = 0; rr < 8; ++rr) {
                const float4 hv = *(const float4*)&sh_h[(g * 8 + rr) * FIN + f4 * 4];
                acc[rr] = fmaf(hv.x, w0, acc[rr]);
                acc[rr] = fmaf(hv.y, w1, acc[rr]);
                acc[rr] = fmaf(hv.z, w2, acc[rr]);
                acc[rr] = fmaf(hv.w, w3, acc[rr]);
            }
        }

#pragma unroll
        for (int rr = 0; rr < 8; ++rr) {
            const int row = row0 + g * 8 + rr;
            g_WhL[(size_t)row * FOUT + o] = acc[rr] * __ldg(&level[row]);
        }
    }
}

// =====================================================================
// Combine 128 partials -> inv; WhLh = fp16(WhL * inv).
// 32 cols per block, transposed coalesced reduction (R13 measured 7.1us).
// grid 512 x 256.
// =====================================================================
__global__ __launch_bounds__(256) void k_comb()
{
    __shared__ float red[8][32];
    __shared__ float sinv[32];
    const int t = threadIdx.x;
    const int col0 = blockIdx.x * 32;
    const int c32 = t & 31;
    const int sl  = t >> 5;

    float s = 0.f;
#pragma unroll
    for (int k = 0; k < SPLIT / 8; ++k)
        s += g_part[(size_t)(sl * (SPLIT / 8) + k) * (BB * NN) + col0 + c32];
    red[sl][c32] = s;
    __syncthreads();

    if (t < 32) {
        float tot = red[0][t];
#pragma unroll
        for (int k = 1; k < 8; ++k) tot += red[k][t];
        sinv[t] = 1.0f / tot;
    }
    __syncthreads();

#pragma unroll
    for (int k = 0; k < 2; ++k) {
        const int idx = t + k * 256;
        const int cc = idx >> 4;
        const int o4 = idx & 15;
        const float inv = sinv[cc];
        const float4 v = ((const float4*)g_WhL)[(size_t)(col0 + cc) * 16 + o4];
        const __half2 h0 = __floats2half2_rn(v.x * inv, v.y * inv);
        const __half2 h1 = __floats2half2_rn(v.z * inv, v.w * inv);
        uint2 u;
        u.x = *(const unsigned int*)&h0;
        u.y = *(const unsigned int*)&h1;
        ((uint2*)g_WhLh)[(size_t)(col0 + cc) * 16 + o4] = u;
    }
}

// =====================================================================
// Kernel C: HMMA partial over a K-slice of 512, ring-3 cp.async pipeline.
// grid (NN/64, BB, SPLITK) = 1024 blocks x 256 threads (4 blocks/SM).
// =====================================================================
#define PITCH 72
#define BUFH (64 * PITCH)

__global__ __launch_bounds__(256) void k_attn()
{
    __shared__ __half Ps[3][BUFH];
    __shared__ __half Ws[3][BUFH];

    const int t = threadIdx.x;
    const int lane = t & 31;
    const int warp = t >> 5;
    const int wr = warp >> 1;
    const int wc = warp & 1;
    const int b  = blockIdx.y;
    const int i0 = blockIdx.x * 64;
    const int ks = blockIdx.z;

    const int r0 = t >> 3, c0 = t & 7;
    const int r1 = r0 + 32;
    const __half* Pg = g_expe + ((size_t)(b * NN + i0)) * NN + ks * KSL;
    const __half* Wg = g_WhLh + ((size_t)(b * NN + ks * KSL)) * FOUT;

    const uint32_t dP0 = smem_u32(&Ps[0][r0 * PITCH + c0 * 8]);
    const uint32_t dP1 = smem_u32(&Ps[0][r1 * PITCH + c0 * 8]);
    const uint32_t dW0 = smem_u32(&Ws[0][r0 * PITCH + c0 * 8]);
    const uint32_t dW1 = smem_u32(&Ws[0][r1 * PITCH + c0 * 8]);
    const uint32_t bufStride = BUFH * sizeof(__half);

    float d[4][4];
#pragma unroll
    for (int n = 0; n < 4; ++n)
#pragma unroll
        for (int k = 0; k < 4; ++k) d[n][k] = 0.f;

    const uint32_t aBase = smem_u32(&Ps[0][(wr * 16 + (lane & 15)) * PITCH + (lane >> 4) * 8]);
    const uint32_t bBase = smem_u32(&Ws[0][(lane & 15) * PITCH + wc * 32 + (lane >> 4) * 8]);

#pragma unroll
    for (int pc = 0; pc < 2; ++pc) {
        const int k0 = pc * 64;
        const uint32_t nb = pc * bufStride;
        cp16(dP0 + nb, Pg + (size_t)r0 * NN + k0 + c0 * 8);
        cp16(dP1 + nb, Pg + (size_t)r1 * NN + k0 + c0 * 8);
        cp16(dW0 + nb, Wg + (size_t)(k0 + r0) * FOUT + c0 * 8);
        cp16(dW1 + nb, Wg + (size_t)(k0 + r1) * FOUT + c0 * 8);
        cp_commit();
    }

    int buf = 0;
    for (int ck = 0; ck < NCHUNK; ++ck) {
        if (ck + 1 < NCHUNK) cp_wait<1>(); else cp_wait<0>();
        __syncthreads();

        if (ck + 2 < NCHUNK) {
            const int k0 = (ck + 2) * 64;
            const int wbuf = (buf + 2 >= 3) ? buf - 1 : buf + 2;
            const uint32_t nb = wbuf * bufStride;
            cp16(dP0 + nb, Pg + (size_t)r0 * NN + k0 + c0 * 8);
            cp16(dP1 + nb, Pg + (size_t)r1 * NN + k0 + c0 * 8);
            cp16(dW0 + nb, Wg + (size_t)(k0 + r0) * FOUT + c0 * 8);
            cp16(dW1 + nb, Wg + (size_t)(k0 + r1) * FOUT + c0 * 8);
            cp_commit();
        }

        const uint32_t aB = aBase + buf * bufStride;
        const uint32_t bB = bBase + buf * bufStride;
#pragma unroll
        for (int kss = 0; kss < 4; ++kss) {
            uint32_t a0, a1, a2, a3;
            asm volatile("ldmatrix.sync.aligned.m8n8.x4.shared.b16 {%0,%1,%2,%3}, [%4];"
                         : "=r"(a0), "=r"(a1), "=r"(a2), "=r"(a3)
                         : "r"(aB + kss * 16 * 2));
#pragma unroll
            for (int np = 0; np < 2; ++np) {
                uint32_t b0, b1, b2, b3;
                asm volatile("ldmatrix.sync.aligned.m8n8.x4.trans.shared.b16 {%0,%1,%2,%3}, [%4];"
                             : "=r"(b0), "=r"(b1), "=r"(b2), "=r"(b3)
                             : "r"(bB + (kss * 16 * PITCH + np * 16) * 2));
                asm volatile("mma.sync.aligned.m16n8k16.row.col.f32.f16.f16.f32 "
                             "{%0,%1,%2,%3}, {%4,%5,%6,%7}, {%8,%9}, {%0,%1,%2,%3};"
                             : "+f"(d[np*2][0]), "+f"(d[np*2][1]), "+f"(d[np*2][2]), "+f"(d[np*2][3])
                             : "r"(a0), "r"(a1), "r"(a2), "r"(a3), "r"(b0), "r"(b1));
                asm volatile("mma.sync.aligned.m16n8k16.row.col.f32.f16.f16.f32 "
                             "{%0,%1,%2,%3}, {%4,%5,%6,%7}, {%8,%9}, {%0,%1,%2,%3};"
                             : "+f"(d[np*2+1][0]), "+f"(d[np*2+1][1]), "+f"(d[np*2+1][2]), "+f"(d[np*2+1][3])
                             : "r"(a0), "r"(a1), "r"(a2), "r"(a3), "r"(b2), "r"(b3));
            }
        }

        buf = (buf + 1 >= 3) ? 0 : buf + 1;
    }

    const int orow = i0 + wr * 16 + (lane >> 2);
    const int ocol = wc * 32 + (lane & 3) * 2;
    float* obase = g_pout + (((size_t)ks * BB + b) * NN + orow) * FOUT + ocol;
#pragma unroll
    for (int nt4 = 0; nt4 < 4; ++nt4) {
        *(float2*)(obase + nt4 * 8) = make_float2(d[nt4][0], d[nt4][1]);
        *(float2*)(obase + (size_t)8 * FOUT + nt4 * 8) = make_float2(d[nt4][2], d[nt4][3]);
    }
}

// =====================================================================
// Combine K-split partials + relu -> out
// =====================================================================
__global__ __launch_bounds__(256) void k_out(float* __restrict__ out)
{
    const int i4 = blockIdx.x * 256 + threadIdx.x;
    const size_t stride4 = (size_t)BB * NN * FOUT / 4;
    float4 s = ((const float4*)g_pout)[i4];
#pragma unroll
    for (int k = 1; k < SPLITK; ++k) {
        const float4 v = ((const float4*)g_pout)[k * stride4 + i4];
        s.x += v.x; s.y += v.y; s.z += v.z; s.w += v.w;
    }
    s.x = fmaxf(s.x, 0.f); s.y = fmaxf(s.y, 0.f);
    s.z = fmaxf(s.z, 0.f); s.w = fmaxf(s.w, 0.f);
    ((float4*)out)[i4] = s;
}

// =====================================================================
extern "C" void kernel_launch(void* const* d_in, const int* in_sizes, int n_in,
                              void* d_out, int out_size)
{
    const float* h     = (const float*)d_in[0];
    const int*   adj   = (const int*)  d_in[1];
    const float* level = (const float*)d_in[2];
    const float* nt    = (const float*)d_in[3];
    const float* W     = (const float*)d_in[4];
    const float* a     = (const float*)d_in[5];
    float* out = (float*)d_out;

    k_wa<<<1, 256>>>(W, a);
    k_f12<<<(BB * NN) / 32, 256>>>(h);
    k_fused<<<CS_BLOCKS + PROJ_BLOCKS, 256>>>(adj, nt, h, W, level);
    k_comb<<<(BB * NN) / 32, 256>>>();
    dim3 ga(NN / 64, BB, SPLITK);
    k_attn<<<ga, 256>>>();
    k_out<<<(BB * NN * FOUT / 4) / 256, 256>>>(out);
}